// round 2
// baseline (speedup 1.0000x reference)
#include <cuda_runtime.h>
#include <float.h>
#include <math.h>

#define A_  64
#define B_  256
#define L_  2000
#define FC1 32     // conv1 out channels
#define FC2 64     // conv2 out channels
#define H_  128
#define KK  5
#define TILE 128
#define NTILE 16   // 16*128 = 2048 >= 2000
#define NF_ 1000000

// ---------------- scratch (device globals; no allocation allowed) ----------
__device__ float g_U[B_ * L_ * A_];          // u[b][l][a], 131 MB
__device__ float g_pmax[B_ * NTILE * A_];    // per-tile max   [b][tile][a]
__device__ float g_psum[B_ * NTILE * A_];    // per-tile sumexp[b][tile][a]
__device__ float g_logZ[B_ * A_];            // logsumexp over l, [b][a]

// ---------------- shared memory layout (bytes) ------------------------------
#define SM_C2S   0                 // float[64][128]        32768
#define SM_HS    32768             // float[128][128]       65536 (aliased by conv bufs)
#define SM_WBUF  98304             // float[128][128]       65536
#define SM_RED   163840            // float[16][64]          4096
#define SM_BM    167936            // float[64]               256
#define SM_TOTAL 168192
// conv-phase aliases inside [SM_HS, SM_WBUF):
#define SM_BINC  (SM_HS)                       // 136 floats (544 B)
#define SM_C1    (SM_HS + 544)                 // float[32][132] (16896 B)
#define SM_C2W   (SM_C1 + 32*132*4)            // float[64*32*5] (40960 B)
#define SM_C1W   (SM_C2W + 10240*4)            // 160 floats
#define SM_C1B   (SM_C1W + 160*4)              // 32 floats
#define SM_C2B   (SM_C1B + 32*4)               // 64 floats

__global__ void __launch_bounds__(256, 1)
fused_kernel(const float* __restrict__ binc_g,
             const float* __restrict__ c1w_g, const float* __restrict__ c1b_g,
             const float* __restrict__ c2w_g, const float* __restrict__ c2b_g,
             const float* __restrict__ l1w_g, const float* __restrict__ l1b_g,
             const float* __restrict__ l2w_g, const float* __restrict__ l2b_g,
             const float* __restrict__ baseline_g,
             const float* __restrict__ diff_g,
             const int*   __restrict__ regions_oi_g)
{
    extern __shared__ char smem[];
    float* c2s   = (float*)(smem + SM_C2S);    // [64][128]  k-major (k=channel, l inner)
    float* hs    = (float*)(smem + SM_HS);     // [128][128] k-major
    float* wbuf  = (float*)(smem + SM_WBUF);   // weights, k-major transposed
    float* red   = (float*)(smem + SM_RED);    // [16][64]
    float* bm    = (float*)(smem + SM_BM);     // [64]
    float* sbinc = (float*)(smem + SM_BINC);
    float* sc1   = (float*)(smem + SM_C1);     // [32][132]
    float* sc2w  = (float*)(smem + SM_C2W);
    float* sc1w  = (float*)(smem + SM_C1W);
    float* sc1b  = (float*)(smem + SM_C1B);
    float* sc2b  = (float*)(smem + SM_C2B);

    const int t       = threadIdx.x;
    const int tileIdx = blockIdx.x;
    const int b       = blockIdx.y;
    const int l0      = tileIdx * TILE;

    // ---- stage conv weights + w1 (wbuf region is free from the start) ----
    for (int i = t; i < FC2 * FC1 * KK; i += 256) sc2w[i] = c2w_g[i];
    if (t < FC1 * KK) sc1w[t] = c1w_g[t];
    if (t < FC1)      sc1b[t] = c1b_g[t];
    if (t < FC2)      sc2b[t] = c2b_g[t];
    // w1^T: wbuf[k][j] = lin1_w[j][k]   (lin1_w is [128][64])
    for (int idx = t; idx < 64 * 128; idx += 256) {
        int j = idx >> 6, k = idx & 63;
        wbuf[k * 128 + j] = l1w_g[idx];
    }
    // bincounts halo slice: global l in [l0-4, l0+132)
    for (int i = t; i < TILE + 8; i += 256) {
        int l = l0 - 4 + i;
        sbinc[i] = (l >= 0 && l < L_) ? binc_g[b * L_ + l] : 0.f;
    }
    __syncthreads();

    // ---- conv1: sc1[ic][j], j in [0,132) <-> l = l0-2+j ----
    // SAME-padding semantics: conv2's input is ZERO outside l in [0, L),
    // so conv1's halo output must be masked to zero there (NOT bias+partial).
    for (int idx = t; idx < FC1 * 132; idx += 256) {
        int ic = idx / 132, j = idx % 132;
        int gl = l0 - 2 + j;
        float acc = sc1b[ic];
        #pragma unroll
        for (int k = 0; k < KK; k++) acc += sbinc[j + k] * sc1w[ic * KK + k];
        sc1[ic * 132 + j] = (gl >= 0 && gl < L_) ? acc : 0.f;
    }
    __syncthreads();

    // ---- conv2: c2s[oc][l], l in [0,128). each item = (oc, 8-l group) ----
    for (int item = t; item < FC2 * 16; item += 256) {
        int oc = item >> 4;
        int lb = (item & 15) * 8;
        float acc[8];
        #pragma unroll
        for (int i = 0; i < 8; i++) acc[i] = sc2b[oc];
        for (int ic = 0; ic < FC1; ic++) {
            float xv[12];
            #pragma unroll
            for (int i = 0; i < 12; i++) xv[i] = sc1[ic * 132 + lb + i];
            #pragma unroll
            for (int k = 0; k < KK; k++) {
                float w = sc2w[(oc * FC1 + ic) * KK + k];
                #pragma unroll
                for (int i = 0; i < 8; i++) acc[i] += xv[i + k] * w;
            }
        }
        #pragma unroll
        for (int i = 0; i < 8; i++) c2s[oc * 128 + lb + i] = acc[i];
    }
    __syncthreads();

    // ---- register-tiled GEMMs: 16x16 threads, 8x8 tiles ----
    const int tx = t & 15, ty = t >> 4;
    const int row0 = ty * 8;     // l within tile
    const int col0 = tx * 8;     // output feature

    // GEMM1: h1[l][j] = relu( sum_k c2s[k][l] * w1t[k][j] + b1[j] ), K=64
    float acc[8][8];
    #pragma unroll
    for (int i = 0; i < 8; i++)
        #pragma unroll
        for (int j = 0; j < 8; j++) acc[i][j] = 0.f;
    for (int k = 0; k < 64; k++) {
        float4 a0 = *(const float4*)&c2s[k * 128 + row0];
        float4 a1 = *(const float4*)&c2s[k * 128 + row0 + 4];
        float4 b0 = *(const float4*)&wbuf[k * 128 + col0];
        float4 b1 = *(const float4*)&wbuf[k * 128 + col0 + 4];
        float av[8] = {a0.x, a0.y, a0.z, a0.w, a1.x, a1.y, a1.z, a1.w};
        float bv[8] = {b0.x, b0.y, b0.z, b0.w, b1.x, b1.y, b1.z, b1.w};
        #pragma unroll
        for (int i = 0; i < 8; i++)
            #pragma unroll
            for (int j = 0; j < 8; j++) acc[i][j] += av[i] * bv[j];
    }
    __syncthreads();   // all k-loop reads of c2s/wbuf/hs-aliases finished

    // epilogue: hs[j][l] = relu(acc + b1[j]); stage w2^T into wbuf
    {
        float bj[8];
        #pragma unroll
        for (int j = 0; j < 8; j++) bj[j] = l1b_g[col0 + j];
        #pragma unroll
        for (int j = 0; j < 8; j++)
            #pragma unroll
            for (int i = 0; i < 8; i++)
                hs[(col0 + j) * 128 + row0 + i] = fmaxf(acc[i][j] + bj[j], 0.f);
    }
    for (int idx = t; idx < 128 * 128; idx += 256) {
        int j = idx >> 7, k = idx & 127;
        wbuf[k * 128 + j] = l2w_g[idx];   // w2t[k][j] = lin2_w[j][k]
    }
    __syncthreads();

    // GEMM2: h2[l][j] = relu( sum_k h1t[k][l] * w2t[k][j] + b2[j] ), K=128
    #pragma unroll
    for (int i = 0; i < 8; i++)
        #pragma unroll
        for (int j = 0; j < 8; j++) acc[i][j] = 0.f;
    for (int k = 0; k < 128; k++) {
        float4 a0 = *(const float4*)&hs[k * 128 + row0];
        float4 a1 = *(const float4*)&hs[k * 128 + row0 + 4];
        float4 b0 = *(const float4*)&wbuf[k * 128 + col0];
        float4 b1 = *(const float4*)&wbuf[k * 128 + col0 + 4];
        float av[8] = {a0.x, a0.y, a0.z, a0.w, a1.x, a1.y, a1.z, a1.w};
        float bv[8] = {b0.x, b0.y, b0.z, b0.w, b1.x, b1.y, b1.z, b1.w};
        #pragma unroll
        for (int i = 0; i < 8; i++)
            #pragma unroll
            for (int j = 0; j < 8; j++) acc[i][j] += av[i] * bv[j];
    }
    __syncthreads();

    {
        float bj[8];
        #pragma unroll
        for (int j = 0; j < 8; j++) bj[j] = l2b_g[col0 + j];
        #pragma unroll
        for (int j = 0; j < 8; j++)
            #pragma unroll
            for (int i = 0; i < 8; i++)
                hs[(col0 + j) * 128 + row0 + i] = fmaxf(acc[i][j] + bj[j], 0.f);
    }
    // stage diff^T: wbuf[k][a] (pitch 64), differential is [64][128]
    for (int idx = t; idx < 64 * 128; idx += 256) {
        int a = idx >> 7, k = idx & 127;
        wbuf[k * 64 + a] = diff_g[idx];
    }
    __syncthreads();

    // GEMM3: u[l][a] = sum_k h2t[k][l] * difft[k][a] + base[b][l], K=128, N=64
    const int col3 = tx * 4;  // a
    float acc3[8][4];
    #pragma unroll
    for (int i = 0; i < 8; i++)
        #pragma unroll
        for (int j = 0; j < 4; j++) acc3[i][j] = 0.f;
    for (int k = 0; k < 128; k++) {
        float4 a0 = *(const float4*)&hs[k * 128 + row0];
        float4 a1 = *(const float4*)&hs[k * 128 + row0 + 4];
        float4 b0 = *(const float4*)&wbuf[k * 64 + col3];
        float av[8] = {a0.x, a0.y, a0.z, a0.w, a1.x, a1.y, a1.z, a1.w};
        float bv[4] = {b0.x, b0.y, b0.z, b0.w};
        #pragma unroll
        for (int i = 0; i < 8; i++)
            #pragma unroll
            for (int j = 0; j < 4; j++) acc3[i][j] += av[i] * bv[j];
    }

    // epilogue: add baseline, write u to global, per-tile logsumexp partials
    const int r = regions_oi_g[b];
    float bval[8];
    bool  valid[8];
    #pragma unroll
    for (int i = 0; i < 8; i++) {
        int gl = l0 + row0 + i;
        valid[i] = (gl < L_);
        bval[i]  = valid[i] ? baseline_g[r * L_ + gl] : 0.f;
    }
    float mloc[4] = {-FLT_MAX, -FLT_MAX, -FLT_MAX, -FLT_MAX};
    #pragma unroll
    for (int i = 0; i < 8; i++) {
        if (!valid[i]) continue;
        int gl = l0 + row0 + i;
        float u0 = acc3[i][0] + bval[i];
        float u1 = acc3[i][1] + bval[i];
        float u2 = acc3[i][2] + bval[i];
        float u3 = acc3[i][3] + bval[i];
        *(float4*)&g_U[(size_t)(b * L_ + gl) * A_ + col3] = make_float4(u0, u1, u2, u3);
        mloc[0] = fmaxf(mloc[0], u0); mloc[1] = fmaxf(mloc[1], u1);
        mloc[2] = fmaxf(mloc[2], u2); mloc[3] = fmaxf(mloc[3], u3);
    }
    #pragma unroll
    for (int j = 0; j < 4; j++) red[ty * 64 + col3 + j] = mloc[j];
    __syncthreads();
    if (t < 64) {
        float m = -FLT_MAX;
        #pragma unroll
        for (int q = 0; q < 16; q++) m = fmaxf(m, red[q * 64 + t]);
        bm[t] = m;
    }
    __syncthreads();
    float bmj[4];
    #pragma unroll
    for (int j = 0; j < 4; j++) bmj[j] = bm[col3 + j];
    float sloc[4] = {0.f, 0.f, 0.f, 0.f};
    #pragma unroll
    for (int i = 0; i < 8; i++) {
        if (!valid[i]) continue;
        #pragma unroll
        for (int j = 0; j < 4; j++)
            sloc[j] += expf(acc3[i][j] + bval[i] - bmj[j]);
    }
    #pragma unroll
    for (int j = 0; j < 4; j++) red[ty * 64 + col3 + j] = sloc[j];
    __syncthreads();
    if (t < 64) {
        float s = 0.f;
        #pragma unroll
        for (int q = 0; q < 16; q++) s += red[q * 64 + t];
        g_pmax[(b * NTILE + tileIdx) * A_ + t] = bm[t];
        g_psum[(b * NTILE + tileIdx) * A_ + t] = s;
    }
}

// combine per-tile partials into logZ[b][a]
__global__ void combine_kernel()
{
    int id = blockIdx.x * blockDim.x + threadIdx.x;
    if (id >= B_ * A_) return;
    int b = id >> 6, a = id & 63;
    float m = -FLT_MAX;
    #pragma unroll
    for (int q = 0; q < NTILE; q++)
        m = fmaxf(m, g_pmax[(b * NTILE + q) * A_ + a]);
    float s = 0.f;
    #pragma unroll
    for (int q = 0; q < NTILE; q++)
        s += g_psum[(b * NTILE + q) * A_ + a] * expf(g_pmax[(b * NTILE + q) * A_ + a] - m);
    g_logZ[b * A_ + a] = m + logf(s);
}

__global__ void gather_kernel(const int* __restrict__ labels,
                              const int* __restrict__ cell_ix,
                              const int* __restrict__ region_ix,
                              const int* __restrict__ binixs,
                              float* __restrict__ out, int nf)
{
    int f = blockIdx.x * blockDim.x + threadIdx.x;
    if (f >= nf) return;
    int a = labels[cell_ix[f]];
    int b = region_ix[f];
    int l = binixs[f];
    out[f] = g_U[(size_t)(b * L_ + l) * A_ + a] - g_logZ[b * A_ + a]
           + 5.545177444479562f;  // + log(B=256)
}

extern "C" void kernel_launch(void* const* d_in, const int* in_sizes, int n_in,
                              void* d_out, int out_size)
{
    const float* bincounts  = (const float*)d_in[0];
    const float* conv1_w    = (const float*)d_in[1];
    const float* conv1_b    = (const float*)d_in[2];
    const float* conv2_w    = (const float*)d_in[3];
    const float* conv2_b    = (const float*)d_in[4];
    const float* lin1_w     = (const float*)d_in[5];
    const float* lin1_b     = (const float*)d_in[6];
    const float* lin2_w     = (const float*)d_in[7];
    const float* lin2_b     = (const float*)d_in[8];
    const float* baseline   = (const float*)d_in[9];
    const float* diff       = (const float*)d_in[10];
    const int*   regions_oi = (const int*)d_in[11];
    const int*   labels     = (const int*)d_in[12];
    const int*   cell_ix    = (const int*)d_in[13];
    const int*   region_ix  = (const int*)d_in[14];
    const int*   binixs     = (const int*)d_in[15];
    float* out = (float*)d_out;
    int nf = in_sizes[13];

    cudaFuncSetAttribute(fused_kernel,
                         cudaFuncAttributeMaxDynamicSharedMemorySize, SM_TOTAL);

    dim3 grid(NTILE, B_);
    fused_kernel<<<grid, 256, SM_TOTAL>>>(bincounts, conv1_w, conv1_b,
                                          conv2_w, conv2_b, lin1_w, lin1_b,
                                          lin2_w, lin2_b, baseline, diff,
                                          regions_oi);
    combine_kernel<<<(B_ * A_ + 255) / 256, 256>>>();
    gather_kernel<<<(nf + 255) / 256, 256>>>(labels, cell_ix, region_ix,
                                             binixs, out, nf);
}

// round 3
// speedup vs baseline: 1.0633x; 1.0633x over previous
#include <cuda_runtime.h>
#include <float.h>
#include <math.h>

#define A_  64
#define B_  256
#define L_  2000
#define FC1 32     // conv1 out channels
#define FC2 64     // conv2 out channels
#define H_  128
#define KK  5
#define TILE 128
#define NTILE 16   // 16*128 = 2048 >= 2000

typedef unsigned long long u64;

// ---------------- scratch (device globals; no allocation allowed) ----------
__device__ float g_U[B_ * L_ * A_];          // u[b][l][a], 131 MB
__device__ float g_pmax[B_ * NTILE * A_];    // per-tile max   [b][tile][a]
__device__ float g_psum[B_ * NTILE * A_];    // per-tile sumexp[b][tile][a]
__device__ float g_logZ[B_ * A_];            // logsumexp over l, [b][a]

// ---------------- shared memory layout (bytes) ------------------------------
#define SM_C2S   0                 // float[64][128]        32768
#define SM_HS    32768             // float[128][128]       65536 (aliased by conv bufs)
#define SM_WBUF  98304             // 16384 floats          65536 (w1dup / w2s / diffdup)
#define SM_RED   163840            // float[16][64]          4096
#define SM_BM    167936            // float[64]               256
#define SM_TOTAL 168192
// conv-phase aliases inside [SM_HS, SM_WBUF):
#define SM_BINC  (SM_HS)                       // 136 floats (544 B)
#define SM_C1    (SM_HS + 544)                 // float[32][132] (16896 B)
#define SM_C2W   (SM_C1 + 32*132*4)            // float2[32*32*5] (40960 B)
#define SM_C1W   (SM_C2W + 5120*8)             // 160 floats
#define SM_C1B   (SM_C1W + 160*4)              // 32 floats
#define SM_C2B   (SM_C1B + 32*4)               // 64 floats

// ---- packed f32x2 helpers ----
__device__ __forceinline__ u64 pk2(float x) {
    u64 r; asm("mov.b64 %0, {%1, %1};" : "=l"(r) : "f"(x)); return r;
}
__device__ __forceinline__ u64 pk2two(float x, float y) {
    u64 r; asm("mov.b64 %0, {%1, %2};" : "=l"(r) : "f"(x), "f"(y)); return r;
}
__device__ __forceinline__ void fma2(u64& d, u64 a, u64 b) {
    asm("fma.rn.f32x2 %0, %1, %2, %0;" : "+l"(d) : "l"(a), "l"(b));
}
__device__ __forceinline__ float2 up(u64 v) {
    float2 f; asm("mov.b64 {%0, %1}, %2;" : "=f"(f.x), "=f"(f.y) : "l"(v)); return f;
}

__global__ void __launch_bounds__(256, 1)
fused_kernel(const float* __restrict__ binc_g,
             const float* __restrict__ c1w_g, const float* __restrict__ c1b_g,
             const float* __restrict__ c2w_g, const float* __restrict__ c2b_g,
             const float* __restrict__ l1w_g, const float* __restrict__ l1b_g,
             const float* __restrict__ l2w_g, const float* __restrict__ l2b_g,
             const float* __restrict__ baseline_g,
             const float* __restrict__ diff_g,
             const int*   __restrict__ regions_oi_g)
{
    extern __shared__ char smem[];
    float* c2s   = (float*)(smem + SM_C2S);    // [64][128]  (oc, l)
    float* hs    = (float*)(smem + SM_HS);     // [128][128] (feat, l)
    float* wbuf  = (float*)(smem + SM_WBUF);   // 16384 floats, phase-dependent layout
    float* red   = (float*)(smem + SM_RED);    // [16][64]
    float* bm    = (float*)(smem + SM_BM);     // [64]
    float* sbinc = (float*)(smem + SM_BINC);
    float* sc1   = (float*)(smem + SM_C1);     // [32][132]
    u64*   sc2wp = (u64*)(smem + SM_C2W);      // float2-packed conv2 weights (oc-pairs)
    float* sc1w  = (float*)(smem + SM_C1W);
    float* sc1b  = (float*)(smem + SM_C1B);
    float* sc2b  = (float*)(smem + SM_C2B);

    const int t       = threadIdx.x;
    const int tileIdx = blockIdx.x;
    const int b       = blockIdx.y;
    const int l0      = tileIdx * TILE;

    // ---- stage conv weights (oc-pair interleaved) + w1 duplicated ----
    // sc2wp[(op*32+ic)*5+k] = {w[2op][ic][k], w[2op+1][ic][k]}
    for (int i = t; i < 32 * 32 * 5; i += 256) {
        int op  = i / 160;
        int rem = i - op * 160;
        int ic  = rem / 5;
        int k   = rem - ic * 5;
        float w0 = c2w_g[(op * 64 + ic) * 5 + k];
        float w1 = c2w_g[(op * 64 + 32 + ic) * 5 + k];
        ((float2*)sc2wp)[i] = make_float2(w0, w1);
    }
    if (t < FC1 * KK) sc1w[t] = c1w_g[t];
    if (t < FC1)      sc1b[t] = c1b_g[t];
    if (t < FC2)      sc2b[t] = c2b_g[t];
    // w1 duplicated, tx-major: j = tx*8 + jg*2 + p  ->
    //   wbuf[(k*4+jg)*64 + tx*4 + p*2 + {0,1}] = w1[j][k]   (lin1_w is [128][64])
    for (int idx = t; idx < 128 * 64; idx += 256) {
        int j = idx >> 6, k = idx & 63;
        float v = l1w_g[idx];
        int jg = (j >> 1) & 3, txw = j >> 3, p = j & 1;
        int base = (k * 4 + jg) * 64 + txw * 4 + p * 2;
        wbuf[base] = v; wbuf[base + 1] = v;
    }
    // bincounts halo slice: global l in [l0-4, l0+132)
    for (int i = t; i < TILE + 8; i += 256) {
        int l = l0 - 4 + i;
        sbinc[i] = (l >= 0 && l < L_) ? binc_g[b * L_ + l] : 0.f;
    }
    __syncthreads();

    // ---- conv1: sc1[ic][j], j in [0,132) <-> l = l0-2+j; halo masked to 0 ----
    for (int idx = t; idx < FC1 * 132; idx += 256) {
        int ic = idx / 132, j = idx % 132;
        int gl = l0 - 2 + j;
        float acc = sc1b[ic];
        #pragma unroll
        for (int k = 0; k < KK; k++) acc += sbinc[j + k] * sc1w[ic * KK + k];
        sc1[ic * 132 + j] = (gl >= 0 && gl < L_) ? acc : 0.f;
    }
    __syncthreads();

    // ---- conv2 (oc-pair packed f32x2): items = (op, 8-l group) ----
    for (int item = t; item < 32 * 16; item += 256) {
        int op = item >> 4;
        int lb = (item & 15) * 8;
        u64 binit = pk2two(sc2b[2 * op], sc2b[2 * op + 1]);
        u64 acc2[8];
        #pragma unroll
        for (int i = 0; i < 8; i++) acc2[i] = binit;
        for (int ic = 0; ic < FC1; ic++) {
            u64 xv2[12];
            #pragma unroll
            for (int i = 0; i < 12; i++) xv2[i] = pk2(sc1[ic * 132 + lb + i]);
            const u64* wp = &sc2wp[(op * 32 + ic) * 5];
            #pragma unroll
            for (int k = 0; k < KK; k++) {
                u64 w2k = wp[k];
                #pragma unroll
                for (int i = 0; i < 8; i++) fma2(acc2[i], xv2[i + k], w2k);
            }
        }
        #pragma unroll
        for (int i = 0; i < 8; i++) {
            float2 r = up(acc2[i]);
            c2s[(2 * op)     * 128 + lb + i] = r.x;
            c2s[(2 * op + 1) * 128 + lb + i] = r.y;
        }
    }
    __syncthreads();

    // ---- register-tiled GEMMs: 16x16 threads, 8x8 thread tiles ----
    const int tx = t & 15, ty = t >> 4;
    const int row0 = ty * 8;     // l within tile
    const int col0 = tx * 8;     // output feature

    // GEMM1 (K=64): i-packed. a pairs from float4; b pre-duplicated in wbuf.
    u64 acc2[4][8];
    #pragma unroll
    for (int i = 0; i < 4; i++)
        #pragma unroll
        for (int j = 0; j < 8; j++) acc2[i][j] = 0ull;
    for (int k = 0; k < 64; k++) {
        ulonglong2 A0 = *(const ulonglong2*)&c2s[k * 128 + row0];
        ulonglong2 A1 = *(const ulonglong2*)&c2s[k * 128 + row0 + 4];
        u64 av2[4] = {A0.x, A0.y, A1.x, A1.y};
        u64 bv2[8];
        #pragma unroll
        for (int jg = 0; jg < 4; jg++) {
            ulonglong2 Bg = *(const ulonglong2*)&wbuf[(k * 4 + jg) * 64 + tx * 4];
            bv2[jg * 2] = Bg.x; bv2[jg * 2 + 1] = Bg.y;
        }
        #pragma unroll
        for (int i = 0; i < 4; i++)
            #pragma unroll
            for (int j = 0; j < 8; j++) fma2(acc2[i][j], av2[i], bv2[j]);
    }
    __syncthreads();   // all k-loop reads of c2s/wbuf finished

    // epilogue: hs[j][l] = relu(acc + b1[j]); stage w2 (tx-major) into wbuf
    {
        #pragma unroll
        for (int j = 0; j < 8; j++) {
            float bj = l1b_g[col0 + j];
            #pragma unroll
            for (int i = 0; i < 4; i++) {
                float2 v = up(acc2[i][j]);
                hs[(col0 + j) * 128 + row0 + 2 * i]     = fmaxf(v.x + bj, 0.f);
                hs[(col0 + j) * 128 + row0 + 2 * i + 1] = fmaxf(v.y + bj, 0.f);
            }
        }
    }
    // w2 tx-major: j = tx*8 + jg*4 + jj -> wbuf[(k*2+jg)*64 + tx*4 + jj]
    for (int idx = t; idx < 128 * 128; idx += 256) {
        int j = idx >> 7, k = idx & 127;
        int jg = (j >> 2) & 1, txw = j >> 3, jj = j & 3;
        wbuf[(k * 2 + jg) * 64 + txw * 4 + jj] = l2w_g[idx];
    }
    __syncthreads();

    // GEMM2 (K=128): j-packed. b pairs aligned from float4; a replicated.
    u64 accB[8][4];
    #pragma unroll
    for (int i = 0; i < 8; i++)
        #pragma unroll
        for (int q = 0; q < 4; q++) accB[i][q] = 0ull;
    for (int k = 0; k < 128; k++) {
        float4 a0 = *(const float4*)&hs[k * 128 + row0];
        float4 a1 = *(const float4*)&hs[k * 128 + row0 + 4];
        u64 av2[8] = {pk2(a0.x), pk2(a0.y), pk2(a0.z), pk2(a0.w),
                      pk2(a1.x), pk2(a1.y), pk2(a1.z), pk2(a1.w)};
        ulonglong2 B0 = *(const ulonglong2*)&wbuf[(k * 2 + 0) * 64 + tx * 4];
        ulonglong2 B1 = *(const ulonglong2*)&wbuf[(k * 2 + 1) * 64 + tx * 4];
        u64 bv2[4] = {B0.x, B0.y, B1.x, B1.y};
        #pragma unroll
        for (int i = 0; i < 8; i++)
            #pragma unroll
            for (int q = 0; q < 4; q++) fma2(accB[i][q], av2[i], bv2[q]);
    }
    __syncthreads();

    {
        #pragma unroll
        for (int q = 0; q < 4; q++) {
            float bx = l2b_g[col0 + 2 * q];
            float by = l2b_g[col0 + 2 * q + 1];
            #pragma unroll
            for (int i = 0; i < 8; i++) {
                float2 v = up(accB[i][q]);
                hs[(col0 + 2 * q)     * 128 + row0 + i] = fmaxf(v.x + bx, 0.f);
                hs[(col0 + 2 * q + 1) * 128 + row0 + i] = fmaxf(v.y + by, 0.f);
            }
        }
    }
    // diff duplicated, tx-major: a = tx*4 + jg*2 + p ->
    //   wbuf[(k*2+jg)*64 + tx*4 + p*2 + {0,1}] = diff[a][k]  (differential [64][128])
    for (int idx = t; idx < 64 * 128; idx += 256) {
        int a = idx >> 7, k = idx & 127;
        float v = diff_g[idx];
        int jg = (a >> 1) & 1, txw = a >> 2, p = a & 1;
        int base = (k * 2 + jg) * 64 + txw * 4 + p * 2;
        wbuf[base] = v; wbuf[base + 1] = v;
    }
    __syncthreads();

    // GEMM3 (K=128, N=64): i-packed, diff pre-duplicated. acc pairs over l.
    const int col3 = tx * 4;  // a
    u64 accC[4][4];
    #pragma unroll
    for (int i = 0; i < 4; i++)
        #pragma unroll
        for (int j = 0; j < 4; j++) accC[i][j] = 0ull;
    for (int k = 0; k < 128; k++) {
        ulonglong2 A0 = *(const ulonglong2*)&hs[k * 128 + row0];
        ulonglong2 A1 = *(const ulonglong2*)&hs[k * 128 + row0 + 4];
        u64 av2[4] = {A0.x, A0.y, A1.x, A1.y};
        ulonglong2 B0 = *(const ulonglong2*)&wbuf[(k * 2 + 0) * 64 + tx * 4];
        ulonglong2 B1 = *(const ulonglong2*)&wbuf[(k * 2 + 1) * 64 + tx * 4];
        u64 bv2[4] = {B0.x, B0.y, B1.x, B1.y};
        #pragma unroll
        for (int i = 0; i < 4; i++)
            #pragma unroll
            for (int j = 0; j < 4; j++) fma2(accC[i][j], av2[i], bv2[j]);
    }

    // epilogue: add baseline, write u, per-tile logsumexp partials
    const int r = regions_oi_g[b];
    float bval[8];
    bool  valid[8];
    #pragma unroll
    for (int i = 0; i < 8; i++) {
        int gl = l0 + row0 + i;
        valid[i] = (gl < L_);
        bval[i]  = valid[i] ? baseline_g[r * L_ + gl] : 0.f;
    }
    float uv[8][4];
    #pragma unroll
    for (int i4 = 0; i4 < 4; i4++) {
        #pragma unroll
        for (int j = 0; j < 4; j++) {
            float2 v = up(accC[i4][j]);
            uv[2 * i4][j]     = v.x + bval[2 * i4];
            uv[2 * i4 + 1][j] = v.y + bval[2 * i4 + 1];
        }
    }
    float mloc[4] = {-FLT_MAX, -FLT_MAX, -FLT_MAX, -FLT_MAX};
    #pragma unroll
    for (int i = 0; i < 8; i++) {
        if (!valid[i]) continue;
        int gl = l0 + row0 + i;
        *(float4*)&g_U[(size_t)(b * L_ + gl) * A_ + col3] =
            make_float4(uv[i][0], uv[i][1], uv[i][2], uv[i][3]);
        #pragma unroll
        for (int j = 0; j < 4; j++) mloc[j] = fmaxf(mloc[j], uv[i][j]);
    }
    #pragma unroll
    for (int j = 0; j < 4; j++) red[ty * 64 + col3 + j] = mloc[j];
    __syncthreads();
    if (t < 64) {
        float m = -FLT_MAX;
        #pragma unroll
        for (int q = 0; q < 16; q++) m = fmaxf(m, red[q * 64 + t]);
        bm[t] = m;
    }
    __syncthreads();
    float bmj[4];
    #pragma unroll
    for (int j = 0; j < 4; j++) bmj[j] = bm[col3 + j];
    float sloc[4] = {0.f, 0.f, 0.f, 0.f};
    #pragma unroll
    for (int i = 0; i < 8; i++) {
        if (!valid[i]) continue;
        #pragma unroll
        for (int j = 0; j < 4; j++) sloc[j] += __expf(uv[i][j] - bmj[j]);
    }
    #pragma unroll
    for (int j = 0; j < 4; j++) red[ty * 64 + col3 + j] = sloc[j];
    __syncthreads();
    if (t < 64) {
        float s = 0.f;
        #pragma unroll
        for (int q = 0; q < 16; q++) s += red[q * 64 + t];
        g_pmax[(b * NTILE + tileIdx) * A_ + t] = bm[t];
        g_psum[(b * NTILE + tileIdx) * A_ + t] = s;
    }
}

// combine per-tile partials into logZ[b][a]
__global__ void combine_kernel()
{
    int id = blockIdx.x * blockDim.x + threadIdx.x;
    if (id >= B_ * A_) return;
    int b = id >> 6, a = id & 63;
    float m = -FLT_MAX;
    #pragma unroll
    for (int q = 0; q < NTILE; q++)
        m = fmaxf(m, g_pmax[(b * NTILE + q) * A_ + a]);
    float s = 0.f;
    #pragma unroll
    for (int q = 0; q < NTILE; q++)
        s += g_psum[(b * NTILE + q) * A_ + a] * __expf(g_pmax[(b * NTILE + q) * A_ + a] - m);
    g_logZ[b * A_ + a] = m + logf(s);
}

__global__ void gather_kernel(const int* __restrict__ labels,
                              const int* __restrict__ cell_ix,
                              const int* __restrict__ region_ix,
                              const int* __restrict__ binixs,
                              float* __restrict__ out, int nf)
{
    int f = blockIdx.x * blockDim.x + threadIdx.x;
    if (f >= nf) return;
    int a = labels[cell_ix[f]];
    int b = region_ix[f];
    int l = binixs[f];
    out[f] = g_U[(size_t)(b * L_ + l) * A_ + a] - g_logZ[b * A_ + a]
           + 5.545177444479562f;  // + log(B=256)
}

extern "C" void kernel_launch(void* const* d_in, const int* in_sizes, int n_in,
                              void* d_out, int out_size)
{
    const float* bincounts  = (const float*)d_in[0];
    const float* conv1_w    = (const float*)d_in[1];
    const float* conv1_b    = (const float*)d_in[2];
    const float* conv2_w    = (const float*)d_in[3];
    const float* conv2_b    = (const float*)d_in[4];
    const float* lin1_w     = (const float*)d_in[5];
    const float* lin1_b     = (const float*)d_in[6];
    const float* lin2_w     = (const float*)d_in[7];
    const float* lin2_b     = (const float*)d_in[8];
    const float* baseline   = (const float*)d_in[9];
    const float* diff       = (const float*)d_in[10];
    const int*   regions_oi = (const int*)d_in[11];
    const int*   labels     = (const int*)d_in[12];
    const int*   cell_ix    = (const int*)d_in[13];
    const int*   region_ix  = (const int*)d_in[14];
    const int*   binixs     = (const int*)d_in[15];
    float* out = (float*)d_out;
    int nf = in_sizes[13];

    cudaFuncSetAttribute(fused_kernel,
                         cudaFuncAttributeMaxDynamicSharedMemorySize, SM_TOTAL);

    dim3 grid(NTILE, B_);
    fused_kernel<<<grid, 256, SM_TOTAL>>>(bincounts, conv1_w, conv1_b,
                                          conv2_w, conv2_b, lin1_w, lin1_b,
                                          lin2_w, lin2_b, baseline, diff,
                                          regions_oi);
    combine_kernel<<<(B_ * A_ + 255) / 256, 256>>>();
    gather_kernel<<<(nf + 255) / 256, 256>>>(labels, cell_ix, region_ix,
                                             binixs, out, nf);
}